// round 12
// baseline (speedup 1.0000x reference)
#include <cuda_runtime.h>
#include <cstdint>

#define NN 64
#define C1 128
#define C2 256
#define H1 56
#define W1 56
#define H2 28
#define W2 28
#define HW1 (H1*W1)        // 3136
#define HW2 (H2*W2)        // 784
#define NPIX (NN*HW2)      // 50176
#define TOT2 (NN*C2*HW2)   // 12845056

// ---------------- scratch (static device globals; no runtime allocation) ----------------
__device__ uint4 g_xb[NN*HW1];         // packed sign(x): [n][h][w], 128 ch -> 4 words
__device__ uint4 g_w1b[9*C2];          // packed sign(w1): [tap][co]
__device__ uint4 g_wsb[C2];            // packed sign(ws): [co]
__device__ unsigned g_w2s8w[9*C2*64];  // sign(w2) as s8 words: [tap][co][ci/4]
__device__ unsigned g_o1s8w[NPIX*64];  // sign(BN1 out) as s8 words: [pix][ch/4]
__device__ short g_t1[NPIX*C2];        // conv1 integer dot: [pix][co]
__device__ float g_part[3*128];        // partial |w| sums (t*128 + blk)
__device__ int g_s1p[98*C2];           // BN1 stats partials: sum
__device__ int g_s1q[98*C2];           // BN1 stats partials: sum of squares
__device__ float g_A1[C2], g_B1[C2];   // BN1 binarize affine
__device__ float g_A2[C2], g_B2[C2];   // BN2 normalize affine

// ---------------- |w| partial sums ----------------
__global__ void k_abs_partial(const float* __restrict__ w1, const float* __restrict__ w2,
                              const float* __restrict__ ws) {
    int t = blockIdx.y;
    const float* s = (t == 0) ? w1 : ((t == 1) ? w2 : ws);
    int n = (t == 0) ? C2*C1*9 : ((t == 1) ? C2*C2*9 : C2*C1);
    float acc = 0.f;
    for (int i = blockIdx.x*blockDim.x + threadIdx.x; i < n; i += gridDim.x*blockDim.x)
        acc += fabsf(s[i]);
    __shared__ float sh[256];
    sh[threadIdx.x] = acc; __syncthreads();
    for (int o = 128; o > 0; o >>= 1) {
        if (threadIdx.x < o) sh[threadIdx.x] += sh[threadIdx.x + o];
        __syncthreads();
    }
    if (threadIdx.x == 0) g_part[t*128 + blockIdx.x] = sh[0];
}

// ---------------- pack w1 bits (tap-major) + ws bits ----------------
__global__ void k_pack_w(const float* __restrict__ w1, const float* __restrict__ ws) {
    int idx = blockIdx.x*blockDim.x + threadIdx.x;
    if (idx < C2*9*4) {
        int co = idx/36, rem = idx%36, tap = rem/4, wd = rem%4;
        unsigned b = 0;
        for (int j = 0; j < 32; j++) {
            float v = w1[(co*C1 + wd*32 + j)*9 + tap];
            b |= (v >= 0.f ? 1u : 0u) << j;
        }
        ((unsigned*)g_w1b)[(tap*C2 + co)*4 + wd] = b;
    } else if (idx < C2*9*4 + C2*4) {
        int k = idx - C2*9*4;
        int co = k/4, wd = k%4;
        unsigned b = 0;
        for (int j = 0; j < 32; j++) {
            float v = ws[co*C1 + wd*32 + j];
            b |= (v >= 0.f ? 1u : 0u) << j;
        }
        ((unsigned*)g_wsb)[co*4 + wd] = b;
    }
}

// ---------------- pack w2 as s8 words: [tap][co][ci/4] ----------------
__global__ void k_pack_w2s8(const float* __restrict__ w2) {
    int idx = blockIdx.x*blockDim.x + threadIdx.x;   // 9*256*64 = 147456
    int tap = idx / 16384, rem = idx % 16384;
    int co = rem / 64, j = rem % 64;
    unsigned w = 0;
    #pragma unroll
    for (int b = 0; b < 4; b++) {
        float v = w2[(co*C2 + j*4 + b)*9 + tap];
        w |= (v >= 0.f ? 0x01u : 0xFFu) << (8*b);
    }
    g_w2s8w[idx] = w;
}

// ---------------- pack sign(x) along channels ----------------
__global__ void k_pack_x(const float* __restrict__ x) {
    int p = blockIdx.x*blockDim.x + threadIdx.x;
    if (p >= NN*HW1) return;
    int n = p / HW1, hw = p - n*HW1;
    const unsigned* xu = (const unsigned*)x;
    unsigned wd[4];
    #pragma unroll
    for (int q = 0; q < 4; q++) {
        unsigned b = 0;
        #pragma unroll 8
        for (int j = 0; j < 32; j++) {
            unsigned u = xu[(n*C1 + q*32 + j)*HW1 + hw];
            b |= ((~u) >> 31) << j;
        }
        wd[q] = b;
    }
    g_xb[p] = make_uint4(wd[0], wd[1], wd[2], wd[3]);
}

// ---------------- conv1: thread = out channel, popc (unchanged from R10) ----------------
__global__ void __launch_bounds__(256, 3) k_conv1() {
    int oh = blockIdx.x, n = blockIdx.y;
    __shared__ uint4 sx[3*W1];
    int tid = threadIdx.x;
    for (int i = tid; i < 3*W1; i += 256) {
        int r = i / W1, c = i - r*W1;
        int ih = 2*oh - 1 + r;
        if (ih >= 0) sx[i] = g_xb[(n*H1 + ih)*W1 + c];
    }
    uint4 w[9];
    #pragma unroll
    for (int t = 0; t < 9; t++) w[t] = g_w1b[t*C2 + tid];
    __syncthreads();
    int obase = (n*HW2 + oh*W2)*C2 + tid;
    for (int ow = 0; ow < W2; ow++) {
        int p0 = 0, p1 = 0, p2 = 0, p3 = 0, nval = 0;
        #pragma unroll
        for (int kh = 0; kh < 3; kh++) {
            #pragma unroll
            for (int kw = 0; kw < 3; kw++) {
                int t = kh*3 + kw;
                int ih = 2*oh - 1 + kh, iw = 2*ow - 1 + kw;
                bool v = (ih >= 0) && (iw >= 0);
                unsigned m = v ? 0xFFFFFFFFu : 0u;
                nval += v ? 1 : 0;
                uint4 xv = sx[kh*W1 + (iw < 0 ? 0 : iw)];
                p0 += __popc((xv.x ^ w[t].x) & m);
                p1 += __popc((xv.y ^ w[t].y) & m);
                p2 += __popc((xv.z ^ w[t].z) & m);
                p3 += __popc((xv.w ^ w[t].w) & m);
            }
        }
        int pop = (p0 + p1) + (p2 + p3);
        g_t1[obase + ow*C2] = (short)(128*nval - 2*pop);
    }
}

// ---------------- BN1 stats stage A ----------------
__global__ void __launch_bounds__(256) k_stats1a() {
    int tid = threadIdx.x;
    int p0 = blockIdx.x * 512;
    int s = 0, s2 = 0;
    #pragma unroll 4
    for (int p = p0; p < p0 + 512; p++) {
        int v = (int)g_t1[p*C2 + tid];
        s += v; s2 += v*v;
    }
    g_s1p[blockIdx.x*C2 + tid] = s;
    g_s1q[blockIdx.x*C2 + tid] = s2;
}

// ---------------- BN1 stats stage B ----------------
__global__ void __launch_bounds__(256) k_stats1b(const float* __restrict__ g1,
                                                 const float* __restrict__ b1) {
    __shared__ float sh[128];
    int tid = threadIdx.x;
    if (tid < 128) sh[tid] = g_part[tid];
    __syncthreads();
    for (int o = 64; o > 0; o >>= 1) { if (tid < o) sh[tid] += sh[tid+o]; __syncthreads(); }
    float a1f = sh[0] / (float)(C2*C1*9);
    long long S = 0, S2 = 0;
    for (int b = 0; b < 98; b++) {
        S  += (long long)g_s1p[b*C2 + tid];
        S2 += (long long)g_s1q[b*C2 + tid];
    }
    double a1 = (double)a1f;
    double mi = (double)S  / (double)NPIX;
    double vi = (double)S2 / (double)NPIX - mi*mi;
    float rs  = (float)(1.0 / sqrt(a1*a1*vi + 1e-5));
    float mus = (float)(a1 * mi);
    float gc = g1[tid];
    g_A1[tid] = a1f * rs * gc;
    g_B1[tid] = b1[tid] - mus * rs * gc;
}

// ---------------- binarize BN1 out -> s8 words [pix][ch/4] ----------------
__global__ void __launch_bounds__(256) k_pack_o1() {
    int tid = threadIdx.x, lane = tid & 31;
    int p0 = blockIdx.x * 32;
    float A = g_A1[tid], B = g_B1[tid];
    for (int i = 0; i < 32; i++) {
        int v = (int)g_t1[(p0 + i)*C2 + tid];
        float o = fmaf(A, (float)v, B);
        unsigned bal = __ballot_sync(0xFFFFFFFFu, o >= 0.f);
        if ((tid & 3) == 0) {
            unsigned e = (~(bal >> lane)) & 15u;   // 1 bits where value is negative
            unsigned w = 0x01010101u
                ^ ((e & 1u) ? 0xFEu : 0u)
                ^ ((e & 2u) ? 0xFE00u : 0u)
                ^ ((e & 4u) ? 0xFE0000u : 0u)
                ^ ((e & 8u) ? 0xFE000000u : 0u);
            g_o1s8w[(p0 + i)*64 + (tid >> 2)] = w;
        }
    }
}

// ---------------- conv2 via s8 tensor-core implicit GEMM + 1x1 popc shortcut ----------------
#define OFFB 48960
#define OFFC 67392
#define OFFXS 87872
#define OFFWS 89664
#define OFFSC 93760
#define SMEMSZ 93768

__device__ __forceinline__ void mma_s8(int& c0, int& c1, int& c2, int& c3,
                                       int a0, int a1, int a2, int a3, int b0, int b1) {
    asm volatile("mma.sync.aligned.m16n8k32.row.col.s32.s8.s8.s32 "
                 "{%0,%1,%2,%3},{%4,%5,%6,%7},{%8,%9},{%0,%1,%2,%3};"
                 : "+r"(c0), "+r"(c1), "+r"(c2), "+r"(c3)
                 : "r"(a0), "r"(a1), "r"(a2), "r"(a3), "r"(b0), "r"(b1));
}

__global__ void __launch_bounds__(256) k_conv2(float* __restrict__ out) {
    extern __shared__ char sm[];
    int8_t* sA   = (int8_t*)sm;                 // [6 rows][30 iw] stride 272, zero-padded
    int*    sB   = (int*)(sm + OFFB);           // 2 x 2304 words, row stride 9 words/co
    float*  sCal = (float*)(sm + OFFC);         // 8 warps x 32x20 floats
    uint4*  sxs  = (uint4*)(sm + OFFXS);        // 112 shortcut pixels
    uint4*  sws  = (uint4*)(sm + OFFWS);        // 256 shortcut weights
    float*  scal = (float*)(sm + OFFSC);

    int tid = threadIdx.x, lane = tid & 31, warp = tid >> 5;
    int oh0 = blockIdx.x * 4, n = blockIdx.y;

    for (int i = tid; i < 48960/16; i += 256) ((uint4*)sA)[i] = make_uint4(0,0,0,0);
    if (tid < 112) {
        int oh = oh0 + tid/28, ow = tid%28;
        sxs[tid] = g_xb[(n*H1 + 2*oh)*W1 + 2*ow];
    }
    sws[tid] = g_wsb[tid];
    if (tid < 32) {
        float v2 = g_part[128+tid]+g_part[160+tid]+g_part[192+tid]+g_part[224+tid];
        float vs = g_part[256+tid]+g_part[288+tid]+g_part[320+tid]+g_part[352+tid];
        #pragma unroll
        for (int o = 16; o > 0; o >>= 1) {
            v2 += __shfl_xor_sync(0xFFFFFFFFu, v2, o);
            vs += __shfl_xor_sync(0xFFFFFFFFu, vs, o);
        }
        if (tid == 0) { scal[0] = v2/(float)(C2*C2*9); scal[1] = vs/(float)(C2*C1); }
    }
    __syncthreads();
    // fill activation rows (interior; borders stay zero)
    for (int r = 0; r < 6; r++) {
        int ih = oh0 - 1 + r;
        if (ih < 0 || ih >= H2) continue;
        int srcb = (n*HW2 + ih*28)*64;
        for (int i = tid; i < 1792; i += 256) {
            int iw = i >> 6, cw = i & 63;
            *(int*)(sA + (r*30 + 1 + iw)*272 + cw*4) = (int)g_o1s8w[srcb + iw*64 + cw];
        }
    }
    // prologue: stage B kstep 0 (tap 0, kc 0)
    unsigned tmp[8];
    #pragma unroll
    for (int jj = 0; jj < 8; jj++) {
        int i = tid + jj*256; int co = i >> 3, j = i & 7;
        tmp[jj] = g_w2s8w[co*64 + j];
    }
    #pragma unroll
    for (int jj = 0; jj < 8; jj++) {
        int i = tid + jj*256; int co = i >> 3, j = i & 7;
        sB[co*9 + j] = (int)tmp[jj];
    }
    int rb_lo[7], rb_hi[7];
    #pragma unroll
    for (int m = 0; m < 7; m++) {
        int p = m*16 + (lane >> 2);
        rb_lo[m] = ((p/28)*30 + p%28)*272 + (lane & 3)*4;
        p += 8;
        rb_hi[m] = ((p/28)*30 + p%28)*272 + (lane & 3)*4;
    }
    int acc[7][4][4];
    #pragma unroll
    for (int m = 0; m < 7; m++)
        #pragma unroll
        for (int nn = 0; nn < 4; nn++)
            #pragma unroll
            for (int r = 0; r < 4; r++) acc[m][nn][r] = 0;

    for (int s = 0; s < 72; s++) {
        __syncthreads();
        const int* sBc = sB + (s & 1)*2304;
        if (s + 1 < 72) {
            int tap1 = (s+1) >> 3, kc1 = (s+1) & 7;
            #pragma unroll
            for (int jj = 0; jj < 8; jj++) {
                int i = tid + jj*256; int co = i >> 3, j = i & 7;
                tmp[jj] = g_w2s8w[(tap1*C2 + co)*64 + kc1*8 + j];
            }
        }
        int tap = s >> 3, kc = s & 7;
        int kh = tap/3, kw = tap - kh*3;
        int toff = (kh*30 + kw)*272 + kc*32;
        int af[7][4];
        #pragma unroll
        for (int m = 0; m < 7; m++) {
            af[m][0] = *(const int*)(sA + rb_lo[m] + toff);
            af[m][1] = *(const int*)(sA + rb_hi[m] + toff);
            af[m][2] = *(const int*)(sA + rb_lo[m] + toff + 16);
            af[m][3] = *(const int*)(sA + rb_hi[m] + toff + 16);
        }
        #pragma unroll
        for (int nn = 0; nn < 4; nn++) {
            int bi = (warp*32 + nn*8 + (lane >> 2))*9 + (lane & 3);
            int b0 = sBc[bi], b1 = sBc[bi + 4];
            #pragma unroll
            for (int m = 0; m < 7; m++)
                mma_s8(acc[m][nn][0], acc[m][nn][1], acc[m][nn][2], acc[m][nn][3],
                       af[m][0], af[m][1], af[m][2], af[m][3], b0, b1);
        }
        if (s + 1 < 72) {
            int* sBn = sB + ((s+1) & 1)*2304;
            #pragma unroll
            for (int jj = 0; jj < 8; jj++) {
                int i = tid + jj*256; int co = i >> 3, j = i & 7;
                sBn[co*9 + j] = (int)tmp[jj];
            }
        }
    }
    __syncthreads();
    // epilogue: shortcut popc + scale, per-warp smem transpose, coalesced NCHW store
    float a2 = scal[0], as_ = scal[1];
    float* sCw = sCal + warp*640;           // 32 x 20
    int n0 = warp*32;
    #pragma unroll
    for (int m = 0; m < 7; m++) {
        #pragma unroll
        for (int nn = 0; nn < 4; nn++) {
            int colb = nn*8 + ((lane & 3) << 1);
            #pragma unroll
            for (int r = 0; r < 4; r++) {
                int pixl = (lane >> 2) + ((r >> 1) << 3);
                int col = colb + (r & 1);
                uint4 xs = sxs[m*16 + pixl];
                uint4 wv = sws[n0 + col];
                int ps = __popc(xs.x ^ wv.x) + __popc(xs.y ^ wv.y)
                       + __popc(xs.z ^ wv.z) + __popc(xs.w ^ wv.w);
                sCw[col*20 + pixl] = fmaf(a2, (float)acc[m][nn][r],
                                          as_ * (float)(128 - 2*ps));
            }
        }
        __syncwarp();
        int pixl = lane & 15, half = lane >> 4;
        int ob = (n*C2 + n0)*HW2 + oh0*28 + m*16 + pixl;
        #pragma unroll
        for (int cc = 0; cc < 16; cc++) {
            int co_l = cc*2 + half;
            out[ob + co_l*HW2] = sCw[co_l*20 + pixl];
        }
        __syncwarp();
    }
}

// ---------------- BN2 stats ----------------
__global__ void __launch_bounds__(512) k_stats2(const float* __restrict__ out,
                                                const float* __restrict__ g2,
                                                const float* __restrict__ b2) {
    int co = blockIdx.x;
    float s = 0.f, s2 = 0.f;
    for (int j = threadIdx.x; j < NN*196; j += 512) {
        int n = j / 196, r = j - n*196;
        float4 v = ((const float4*)&out[(n*C2 + co)*HW2])[r];
        s += (v.x + v.y) + (v.z + v.w);
        s2 = fmaf(v.x, v.x, fmaf(v.y, v.y, fmaf(v.z, v.z, fmaf(v.w, v.w, s2))));
    }
    __shared__ double sa[512], sb[512];
    sa[threadIdx.x] = (double)s; sb[threadIdx.x] = (double)s2; __syncthreads();
    for (int o = 256; o > 0; o >>= 1) {
        if (threadIdx.x < o) { sa[threadIdx.x] += sa[threadIdx.x+o]; sb[threadIdx.x] += sb[threadIdx.x+o]; }
        __syncthreads();
    }
    if (threadIdx.x == 0) {
        double m = sa[0] / (double)NPIX;
        double var = sb[0] / (double)NPIX - m*m;
        float rs = (float)(1.0 / sqrt(var + 1e-5));
        float mus = (float)m;
        float gc = g2[co];
        g_A2[co] = rs * gc;
        g_B2[co] = b2[co] - mus * rs * gc;
    }
}

// ---------------- final BN2 normalize ----------------
__global__ void k_norm(float* __restrict__ out) {
    int i = blockIdx.x*blockDim.x + threadIdx.x;
    if (i >= TOT2/4) return;
    int c = (i / (HW2/4)) & (C2 - 1);
    float A = g_A2[c], B = g_B2[c];
    float4 v = ((float4*)out)[i];
    v.x = fmaf(v.x, A, B); v.y = fmaf(v.y, A, B);
    v.z = fmaf(v.z, A, B); v.w = fmaf(v.w, A, B);
    ((float4*)out)[i] = v;
}

// ---------------- launch ----------------
extern "C" void kernel_launch(void* const* d_in, const int* in_sizes, int n_in,
                              void* d_out, int out_size) {
    const float* x  = (const float*)d_in[0];
    const float* w1 = (const float*)d_in[1];
    const float* g1 = (const float*)d_in[2];
    const float* b1 = (const float*)d_in[3];
    const float* w2 = (const float*)d_in[4];
    const float* g2 = (const float*)d_in[5];
    const float* b2 = (const float*)d_in[6];
    const float* ws = (const float*)d_in[7];
    float* out = (float*)d_out;

    cudaFuncSetAttribute(k_conv2, cudaFuncAttributeMaxDynamicSharedMemorySize, SMEMSZ);

    k_abs_partial<<<dim3(128, 3), 256>>>(w1, w2, ws);
    k_pack_w<<<40, 256>>>(w1, ws);
    k_pack_w2s8<<<576, 256>>>(w2);
    k_pack_x<<<(NN*HW1 + 255)/256, 256>>>(x);
    k_conv1<<<dim3(H2, NN), 256>>>();
    k_stats1a<<<98, 256>>>();
    k_stats1b<<<1, 256>>>(g1, b1);
    k_pack_o1<<<NPIX/32, 256>>>();
    k_conv2<<<dim3(7, NN), 256, SMEMSZ>>>(out);
    k_stats2<<<C2, 512>>>(out, g2, b2);
    k_norm<<<(TOT2/4 + 255)/256, 256>>>(out);
}

// round 13
// speedup vs baseline: 1.8314x; 1.8314x over previous
#include <cuda_runtime.h>
#include <cstdint>

#define NN 64
#define C1 128
#define C2 256
#define H1 56
#define W1 56
#define H2 28
#define W2 28
#define HW1 (H1*W1)        // 3136
#define HW2 (H2*W2)        // 784
#define NPIX (NN*HW2)      // 50176
#define TOT2 (NN*C2*HW2)   // 12845056

// ---------------- scratch (static device globals; no runtime allocation) ----------------
__device__ uint4 g_xb[NN*HW1];       // packed sign(x): [n][h][w], 128 ch -> 4 words
__device__ uint4 g_w1b[9*C2];        // packed sign(w1): [tap][co]
__device__ uint4 g_w2b[9*2*C2];      // packed sign(w2): [tap][half][co]
__device__ uint4 g_wsb[C2];          // packed sign(ws): [co]
__device__ unsigned g_o1b[8*NPIX];   // packed sign(BN1 out): [q][n*HW2+hw]
__device__ short g_t1[NPIX*C2];      // conv1 integer dot: [pix][co]
__device__ float g_part[3*128];      // partial |w| sums (t*128 + blk)
__device__ unsigned long long g_s1sum[C2];  // BN1 stats: exact int64 sum (atomic)
__device__ unsigned long long g_s1sq[C2];   // BN1 stats: exact int64 sum of squares
__device__ float g_A1[C2], g_B1[C2]; // BN1 binarize affine: sign(A1*I + B1)
__device__ float g_A2[C2], g_B2[C2]; // BN2 normalize affine: v*A2 + B2

// ---------------- zero BN1 atomic accumulators (graph replays must reset) ----------------
__global__ void k_zero1() {
    int i = threadIdx.x;
    if (i < C2) { g_s1sum[i] = 0ull; g_s1sq[i] = 0ull; }
}

// ---------------- |w| partial sums ----------------
__global__ void k_abs_partial(const float* __restrict__ w1, const float* __restrict__ w2,
                              const float* __restrict__ ws) {
    int t = blockIdx.y;
    const float* s = (t == 0) ? w1 : ((t == 1) ? w2 : ws);
    int n = (t == 0) ? C2*C1*9 : ((t == 1) ? C2*C2*9 : C2*C1);
    float acc = 0.f;
    for (int i = blockIdx.x*blockDim.x + threadIdx.x; i < n; i += gridDim.x*blockDim.x)
        acc += fabsf(s[i]);
    __shared__ float sh[256];
    sh[threadIdx.x] = acc; __syncthreads();
    for (int o = 128; o > 0; o >>= 1) {
        if (threadIdx.x < o) sh[threadIdx.x] += sh[threadIdx.x + o];
        __syncthreads();
    }
    if (threadIdx.x == 0) g_part[t*128 + blockIdx.x] = sh[0];
}

// ---------------- pack weight sign bits (tap-major layouts) ----------------
__global__ void k_pack_w(const float* __restrict__ w1, const float* __restrict__ w2,
                         const float* __restrict__ ws) {
    int idx = blockIdx.x*blockDim.x + threadIdx.x;
    if (idx < C2*9*4) {
        int co = idx/36, rem = idx%36, tap = rem/4, wd = rem%4;
        unsigned b = 0;
        for (int j = 0; j < 32; j++) {
            float v = w1[(co*C1 + wd*32 + j)*9 + tap];
            b |= (v >= 0.f ? 1u : 0u) << j;
        }
        ((unsigned*)g_w1b)[(tap*C2 + co)*4 + wd] = b;
    } else if (idx < C2*9*4 + C2*9*8) {
        int k = idx - C2*9*4;
        int co = k/72, rem = k%72, tap = rem/8, wd = rem%8;
        unsigned b = 0;
        for (int j = 0; j < 32; j++) {
            float v = w2[(co*C2 + wd*32 + j)*9 + tap];
            b |= (v >= 0.f ? 1u : 0u) << j;
        }
        ((unsigned*)g_w2b)[((tap*2 + (wd>>2))*C2 + co)*4 + (wd&3)] = b;
    } else if (idx < C2*9*4 + C2*9*8 + C2*4) {
        int k = idx - (C2*9*4 + C2*9*8);
        int co = k/4, wd = k%4;
        unsigned b = 0;
        for (int j = 0; j < 32; j++) {
            float v = ws[co*C1 + wd*32 + j];
            b |= (v >= 0.f ? 1u : 0u) << j;
        }
        ((unsigned*)g_wsb)[co*4 + wd] = b;
    }
}

// ---------------- pack sign(x) along channels ----------------
__global__ void k_pack_x(const float* __restrict__ x) {
    int p = blockIdx.x*blockDim.x + threadIdx.x;
    if (p >= NN*HW1) return;
    int n = p / HW1, hw = p - n*HW1;
    const unsigned* xu = (const unsigned*)x;
    unsigned wd[4];
    #pragma unroll
    for (int q = 0; q < 4; q++) {
        unsigned b = 0;
        #pragma unroll 8
        for (int j = 0; j < 32; j++) {
            unsigned u = xu[(n*C1 + q*32 + j)*HW1 + hw];
            b |= ((~u) >> 31) << j;
        }
        wd[q] = b;
    }
    g_xb[p] = make_uint4(wd[0], wd[1], wd[2], wd[3]);
}

// ---------------- conv1: thread = out channel, weights in regs; fused BN1 stats ----------------
__global__ void __launch_bounds__(256, 3) k_conv1() {
    int oh = blockIdx.x, n = blockIdx.y;
    __shared__ uint4 sx[3*W1];          // rows ih = 2oh-1, 2oh, 2oh+1
    int tid = threadIdx.x;
    for (int i = tid; i < 3*W1; i += 256) {
        int r = i / W1, c = i - r*W1;
        int ih = 2*oh - 1 + r;
        if (ih >= 0) sx[i] = g_xb[(n*H1 + ih)*W1 + c];
    }
    uint4 w[9];
    #pragma unroll
    for (int t = 0; t < 9; t++) w[t] = g_w1b[t*C2 + tid];   // coalesced
    __syncthreads();
    int obase = (n*HW2 + oh*W2)*C2 + tid;
    int s = 0, s2 = 0;                   // per-thread stats (max 28*1152^2 < 2^31)
    for (int ow = 0; ow < W2; ow++) {
        int p0 = 0, p1 = 0, p2 = 0, p3 = 0, nval = 0;
        #pragma unroll
        for (int kh = 0; kh < 3; kh++) {
            #pragma unroll
            for (int kw = 0; kw < 3; kw++) {
                int t = kh*3 + kw;
                int ih = 2*oh - 1 + kh, iw = 2*ow - 1 + kw;
                bool v = (ih >= 0) && (iw >= 0);
                unsigned m = v ? 0xFFFFFFFFu : 0u;
                nval += v ? 1 : 0;
                uint4 xv = sx[kh*W1 + (iw < 0 ? 0 : iw)];   // broadcast LDS
                p0 += __popc((xv.x ^ w[t].x) & m);
                p1 += __popc((xv.y ^ w[t].y) & m);
                p2 += __popc((xv.z ^ w[t].z) & m);
                p3 += __popc((xv.w ^ w[t].w) & m);
            }
        }
        int pop = (p0 + p1) + (p2 + p3);
        int d = 128*nval - 2*pop;
        g_t1[obase + ow*C2] = (short)d;  // coalesced 512B store
        s += d; s2 += d*d;
    }
    // exact integer atomics: order-invariant => deterministic
    atomicAdd(&g_s1sum[tid], (unsigned long long)(long long)s);
    atomicAdd(&g_s1sq[tid],  (unsigned long long)(long long)s2);
}

// ---------------- BN1 stats finalize (+ alpha1 reduce) ----------------
__global__ void __launch_bounds__(256) k_stats1b(const float* __restrict__ g1,
                                                 const float* __restrict__ b1) {
    __shared__ float sh[128];
    int tid = threadIdx.x;
    if (tid < 128) sh[tid] = g_part[tid];
    __syncthreads();
    for (int o = 64; o > 0; o >>= 1) { if (tid < o) sh[tid] += sh[tid+o]; __syncthreads(); }
    float a1f = sh[0] / (float)(C2*C1*9);
    long long S  = (long long)g_s1sum[tid];
    long long S2 = (long long)g_s1sq[tid];
    double a1 = (double)a1f;
    double mi = (double)S  / (double)NPIX;
    double vi = (double)S2 / (double)NPIX - mi*mi;
    float rs  = (float)(1.0 / sqrt(a1*a1*vi + 1e-5));
    float mus = (float)(a1 * mi);
    float gc = g1[tid];
    g_A1[tid] = a1f * rs * gc;
    g_B1[tid] = b1[tid] - mus * rs * gc;
}

// ---------------- binarize+pack BN1 output: coalesced loads + ballot, q-major store ----------------
__global__ void __launch_bounds__(256) k_pack_o1() {
    int tid = threadIdx.x, wq = tid >> 5, lane = tid & 31;
    int p0 = blockIdx.x * 32;
    float A = g_A1[tid], B = g_B1[tid];
    unsigned myword = 0;
    #pragma unroll 4
    for (int i = 0; i < 32; i++) {
        int v = (int)g_t1[(p0 + i)*C2 + tid];   // coalesced 64B/warp
        float o = fmaf(A, (float)v, B);
        unsigned w = __ballot_sync(0xFFFFFFFFu, o >= 0.f);
        if (lane == i) myword = w;
    }
    g_o1b[wq*NPIX + p0 + lane] = myword;        // coalesced 128B/warp
}

// ---------------- conv2 + 1x1 shortcut: thread = out channel, weights in regs ----------------
__global__ void __launch_bounds__(256, 2) k_conv2(float* __restrict__ out) {
    int oh = blockIdx.x, n = blockIdx.y;
    __shared__ uint4 sxq[3*W2*2];       // [(r*W2+iw)*2 + half], 8 words per input pixel
    __shared__ uint4 sxs[W2];           // shortcut packed x per ow
    __shared__ float sres[C2*29];       // padded stride 29: conflict-free
    __shared__ float s_a2, s_as;
    int tid = threadIdx.x;
    for (int i = tid; i < 3*W2*8; i += 256) {
        int q = i & 7; int rem = i >> 3; int iw = rem % W2, r = rem / W2;
        int ih = oh - 1 + r;
        ((unsigned*)sxq)[(r*W2 + iw)*8 + q] =
            (ih >= 0 && ih < H2) ? g_o1b[q*NPIX + n*HW2 + ih*W2 + iw] : 0u;
    }
    if (tid < W2) sxs[tid] = g_xb[(n*H1 + 2*oh)*W1 + 2*tid];
    uint4 wa[9], wb[9];
    #pragma unroll
    for (int t = 0; t < 9; t++) {
        wa[t] = g_w2b[(t*2 + 0)*C2 + tid];      // coalesced
        wb[t] = g_w2b[(t*2 + 1)*C2 + tid];
    }
    uint4 wv = g_wsb[tid];
    if (tid < 32) {
        float v2 = g_part[128+tid] + g_part[160+tid] + g_part[192+tid] + g_part[224+tid];
        float vs = g_part[256+tid] + g_part[288+tid] + g_part[320+tid] + g_part[352+tid];
        #pragma unroll
        for (int o = 16; o > 0; o >>= 1) {
            v2 += __shfl_xor_sync(0xFFFFFFFFu, v2, o);
            vs += __shfl_xor_sync(0xFFFFFFFFu, vs, o);
        }
        if (tid == 0) { s_a2 = v2 / (float)(C2*C2*9); s_as = vs / (float)(C2*C1); }
    }
    __syncthreads();
    float a2 = s_a2, as_ = s_as;
    for (int ow = 0; ow < W2; ow++) {
        int p0 = 0, p1 = 0, p2 = 0, p3 = 0, nval = 0;
        #pragma unroll
        for (int kh = 0; kh < 3; kh++) {
            #pragma unroll
            for (int kw = 0; kw < 3; kw++) {
                int t = kh*3 + kw;
                int ih = oh - 1 + kh, iw = ow - 1 + kw;
                bool v = ((unsigned)ih < H2) && ((unsigned)iw < W2);
                unsigned m = v ? 0xFFFFFFFFu : 0u;
                nval += v ? 1 : 0;
                int iwc = iw < 0 ? 0 : (iw > W2-1 ? W2-1 : iw);
                uint4 lo = sxq[(kh*W2 + iwc)*2];        // broadcast LDS
                uint4 hi = sxq[(kh*W2 + iwc)*2 + 1];
                p0 += __popc((lo.x ^ wa[t].x) & m) + __popc((hi.x ^ wb[t].x) & m);
                p1 += __popc((lo.y ^ wa[t].y) & m) + __popc((hi.y ^ wb[t].y) & m);
                p2 += __popc((lo.z ^ wa[t].z) & m) + __popc((hi.z ^ wb[t].z) & m);
                p3 += __popc((lo.w ^ wa[t].w) & m) + __popc((hi.w ^ wb[t].w) & m);
            }
        }
        int pop = (p0 + p1) + (p2 + p3);
        uint4 xs = sxs[ow];
        int ps = __popc(xs.x ^ wv.x) + __popc(xs.y ^ wv.y)
               + __popc(xs.z ^ wv.z) + __popc(xs.w ^ wv.w);
        sres[tid*29 + ow] = fmaf(a2, (float)(256*nval - 2*pop), as_ * (float)(128 - 2*ps));
    }
    __syncthreads();
    int ob = (n*C2)*HW2 + oh*W2;
    for (int i = tid; i < C2*W2; i += 256) {
        int col = i / W2, px = i - col*W2;
        out[ob + col*HW2 + px] = sres[col*29 + px];
    }
}

// ---------------- BN2 stats: float4 loads, f32 per-thread, double block tree ----------------
__global__ void __launch_bounds__(512) k_stats2(const float* __restrict__ out,
                                                const float* __restrict__ g2,
                                                const float* __restrict__ b2) {
    int co = blockIdx.x;
    float s = 0.f, s2 = 0.f;
    for (int j = threadIdx.x; j < NN*196; j += 512) {
        int n = j / 196, r = j - n*196;
        float4 v = ((const float4*)&out[(n*C2 + co)*HW2])[r];
        s += (v.x + v.y) + (v.z + v.w);
        s2 = fmaf(v.x, v.x, fmaf(v.y, v.y, fmaf(v.z, v.z, fmaf(v.w, v.w, s2))));
    }
    __shared__ double sa[512], sb[512];
    sa[threadIdx.x] = (double)s; sb[threadIdx.x] = (double)s2; __syncthreads();
    for (int o = 256; o > 0; o >>= 1) {
        if (threadIdx.x < o) { sa[threadIdx.x] += sa[threadIdx.x+o]; sb[threadIdx.x] += sb[threadIdx.x+o]; }
        __syncthreads();
    }
    if (threadIdx.x == 0) {
        double m = sa[0] / (double)NPIX;
        double var = sb[0] / (double)NPIX - m*m;
        float rs = (float)(1.0 / sqrt(var + 1e-5));
        float mus = (float)m;
        float gc = g2[co];
        g_A2[co] = rs * gc;
        g_B2[co] = b2[co] - mus * rs * gc;
    }
}

// ---------------- final BN2 normalize (in-place, float4) ----------------
__global__ void k_norm(float* __restrict__ out) {
    int i = blockIdx.x*blockDim.x + threadIdx.x;
    if (i >= TOT2/4) return;
    int c = (i / (HW2/4)) & (C2 - 1);
    float A = g_A2[c], B = g_B2[c];
    float4 v = ((float4*)out)[i];
    v.x = fmaf(v.x, A, B); v.y = fmaf(v.y, A, B);
    v.z = fmaf(v.z, A, B); v.w = fmaf(v.w, A, B);
    ((float4*)out)[i] = v;
}

// ---------------- launch ----------------
extern "C" void kernel_launch(void* const* d_in, const int* in_sizes, int n_in,
                              void* d_out, int out_size) {
    const float* x  = (const float*)d_in[0];
    const float* w1 = (const float*)d_in[1];
    const float* g1 = (const float*)d_in[2];
    const float* b1 = (const float*)d_in[3];
    const float* w2 = (const float*)d_in[4];
    const float* g2 = (const float*)d_in[5];
    const float* b2 = (const float*)d_in[6];
    const float* ws = (const float*)d_in[7];
    float* out = (float*)d_out;

    k_zero1<<<1, 256>>>();
    k_abs_partial<<<dim3(128, 3), 256>>>(w1, w2, ws);
    k_pack_w<<<112, 256>>>(w1, w2, ws);
    k_pack_x<<<(NN*HW1 + 255)/256, 256>>>(x);
    k_conv1<<<dim3(H2, NN), 256>>>();
    k_stats1b<<<1, 256>>>(g1, b1);
    k_pack_o1<<<NPIX/32, 256>>>();
    k_conv2<<<dim3(H2, NN), 256>>>(out);
    k_stats2<<<C2, 512>>>(out, g2, b2);
    k_norm<<<(TOT2/4 + 255)/256, 256>>>(out);
}